// round 15
// baseline (speedup 1.0000x reference)
#include <cuda_runtime.h>
#include <cstdint>

// MedianFilterLoss, decomposed:
//   loss = sum_i softplus((1-2*t_i)*x_i)                       (base, elementwise)
//        - sum_{runs of ones, len>=3} max-weight subset of w_i = relu(-x_i)
//          with pairwise distance >= 3 (3-state max-plus DP per run)
// 4096-elem tiles, 5 CTAs/SM. Phase 1 is pure cp.async issue of raw x,t into
// padded smem (all DRAM requests up-front); phase 2 is one fused pass doing
// softplus + enc + DP straight from smem. DP reset = -0.0f; "len>=3" ==
// sign(m0)>=0. Prefix runs: close suppressed (owned by previous thread).

#define T_LEN 16384
#define TILE  4096
#define NTH   256
#define EPT   16
#define ROWF  20                       // words per thread-row: 16 data + 4 pad (80B)
#define XW    (NTH * ROWF)             // 5120 words per array
#define XB    (XW * 4)                 // 20480 bytes
#define NEGZ  __int_as_float(0x80000000)
#define LN2F  0.6931471805599453f

__device__ float g_partial[4096];
__device__ unsigned int g_done;

__device__ __forceinline__ void cp16(uint32_t dst, const void* src) {
    asm volatile("cp.async.cg.shared.global [%0], [%1], 16;\n" :: "r"(dst), "l"(src));
}

__global__ void __launch_bounds__(NTH, 5) mfl_fused(const float* __restrict__ xg,
                                                    const int* __restrict__ tg,
                                                    float* __restrict__ o,
                                                    double inv_n) {
    __shared__ float sbuf[2 * XW];     // [0,XW): x raw, [XW,2XW): t raw (padded rows)
    __shared__ float wsum[NTH / 32];
    __shared__ double sdbl[NTH];
    __shared__ unsigned int s_last;

    const int tile = blockIdx.x;
    const int row  = tile >> 2;        // tensor row (4 tiles per row)
    const int qtr  = tile & 3;
    const int base = row * T_LEN + qtr * TILE;
    const int tid  = threadIdx.x;
    const int lane = tid & 31;
    const int wid  = tid >> 5;

    uint32_t sbase;
    asm("{ .reg .u64 t0; cvta.to.shared.u64 t0, %1; cvt.u32.u64 %0, t0; }"
        : "=r"(sbase) : "l"(sbuf));

    // previous target bit (prefetch overlaps the cp.async drain)
    int prevt = 0;
    if (tid == 0 && qtr != 0) prevt = tg[base - 1];

    // ---- Phase 1: pure cp.async issue (raw x and t, 16B chunks) ----
    const char* xsrc = (const char*)(xg + base);
    const char* tsrc = (const char*)(tg + base);
#pragma unroll
    for (int k = 0; k < 4; ++k) {
        int g = k * NTH + tid;                 // 16B-chunk index, [0,1024)
        uint32_t d = sbase + (uint32_t)(g >> 2) * 80u + (uint32_t)(g & 3) * 16u;
        long so = (long)g * 16;
        cp16(d,      xsrc + so);
        cp16(d + XB, tsrc + so);
    }
    asm volatile("cp.async.commit_group;\n");
    asm volatile("cp.async.wait_group 0;\n");
    __syncthreads();

    // ---- Phase 2: fused softplus + DP over 16 contiguous elements ----
    const float* bx = sbuf;
    const int*   bt = (const int*)(sbuf + XW);
    const float* myx = bx + tid * ROWF;
    const int*   myt = bt + tid * ROWF;

    float acc  = 0.0f;                 // relu terms + DP corrections
    float accL = 0.0f;                 // log2 terms, * ln2 at the end

    bool suppress;
    if (tid == 0) suppress = (prevt != 0);
    else          suppress = (bt[(tid - 1) * ROWF + (EPT - 1)] != 0);

    float m0 = NEGZ, m1 = NEGZ, m2 = NEGZ;
    bool b = false;
#pragma unroll
    for (int j = 0; j < 4; ++j) {              // 4 x LDS.128 per array
        float4 xq = reinterpret_cast<const float4*>(myx)[j];
        int4   tq = reinterpret_cast<const int4*>(myt)[j];
        float xv[4] = {xq.x, xq.y, xq.z, xq.w};
        int   tv[4] = {tq.x, tq.y, tq.z, tq.w};
#pragma unroll
        for (int e = 0; e < 4; ++e) {
            float x = xv[e];
            b = (tv[e] != 0);
            float u = exp2f(fabsf(x) * -1.4426950408889634f);
            accL   += __log2f(1.0f + u);
            float s = b ? -x : x;
            float r = fmaxf(s, 0.0f);
            acc    += r;
            bool doclose = !b && !suppress && (__float_as_int(m0) >= 0);
            if (doclose) acc -= m2;
            suppress = suppress && b;
            float nm2 = fabsf(fmaxf(m2, m0 + r));
            m0 = b ? m1 : NEGZ;
            m1 = b ? m2 : NEGZ;
            m2 = b ? nm2 : NEGZ;
        }
    }

    // ---- suffix: open run at chunk end ----
    if (b && !suppress) {
        bool alive = true;
        if (tid < NTH - 1) {
            // 8-element register overlap into next thread's row
            const float* nx = myx + ROWF;
            const int*   nt = myt + ROWF;
#pragma unroll
            for (int j = 0; j < 2; ++j) {
                float4 xq = reinterpret_cast<const float4*>(nx)[j];
                int4   tq = reinterpret_cast<const int4*>(nt)[j];
                float xv[4] = {xq.x, xq.y, xq.z, xq.w};
                int   tv[4] = {tq.x, tq.y, tq.z, tq.w};
#pragma unroll
                for (int e = 0; e < 4; ++e) {
                    bool one = (tv[e] != 0);
                    float r = fmaxf(-xv[e], 0.0f);
                    bool cont = alive && one;
                    bool cls  = alive && !one && (__float_as_int(m0) >= 0);
                    if (cls) acc -= m2;
                    float nm2 = fabsf(fmaxf(m2, m0 + r));
                    m0 = cont ? m1 : m0;
                    m1 = cont ? m2 : m1;
                    m2 = cont ? nm2 : m2;
                    alive = cont;
                }
            }
        }
        if (alive) {                            // rare: run alive past +8
            int p = (tid + 1) * EPT + ((tid < NTH - 1) ? 8 : 0);
            while (p < TILE) {
                int idx = (p >> 4) * ROWF + (p & 15);
                if (bt[idx] == 0) break;
                float r = fmaxf(-bx[idx], 0.0f);
                float nm2 = fabsf(fmaxf(m2, m0 + r));
                m0 = m1; m1 = m2; m2 = nm2; ++p;
            }
            if (p == TILE && qtr != 3) {        // spill past tile into same row
                int g = base + TILE;
                const int gend = row * T_LEN + T_LEN;
                while (g < gend && tg[g] != 0) {
                    float w = fmaxf(-xg[g], 0.0f);
                    float nm2 = fabsf(fmaxf(m2, m0 + w));
                    m0 = m1; m1 = m2; m2 = nm2; ++g;
                }
            }
            if (__float_as_int(m0) >= 0) acc -= m2;   // close at zero / row end
        }
    }

    acc = fmaf(accL, LN2F, acc);

    // ---- block reduction ----
#pragma unroll
    for (int off = 16; off; off >>= 1)
        acc += __shfl_down_sync(0xFFFFFFFFu, acc, off);
    if (lane == 0) wsum[wid] = acc;
    __syncthreads();
    float blocksum = 0.0f;
    if (wid == 0) {
        float v = (lane < NTH / 32) ? wsum[lane] : 0.0f;
#pragma unroll
        for (int off = 4; off; off >>= 1)
            v += __shfl_down_sync(0xFFFFFFFFu, v, off);
        blocksum = v;
    }

    // ---- last-block-done final reduction (single launch) ----
    if (tid == 0) {
        g_partial[blockIdx.x] = blocksum;
        __threadfence();
        unsigned old = atomicAdd(&g_done, 1u);
        s_last = (old == gridDim.x - 1) ? 1u : 0u;
    }
    __syncthreads();
    if (s_last) {
        const volatile float* gp = g_partial;
        double sv = 0.0;
        for (int i = tid; i < (int)gridDim.x; i += NTH)
            sv += (double)gp[i];
        sdbl[tid] = sv;
        __syncthreads();
#pragma unroll
        for (int off = NTH / 2; off; off >>= 1) {
            if (tid < off) sdbl[tid] += sdbl[tid + off];
            __syncthreads();
        }
        if (tid == 0) {
            o[0] = (float)(sdbl[0] * inv_n);
            g_done = 0;                         // reset for next graph replay
        }
    }
}

extern "C" void kernel_launch(void* const* d_in, const int* in_sizes, int n_in,
                              void* d_out, int out_size) {
    const float* xg = (const float*)d_in[0];
    const int*   tg = (const int*)d_in[1];
    long long n = (long long)in_sizes[0];      // 1024 * 16384
    int grid = (int)(n / TILE);                // 4096
    mfl_fused<<<grid, NTH>>>(xg, tg, (float*)d_out, 1.0 / (double)n);
}

// round 17
// speedup vs baseline: 1.0563x; 1.0563x over previous
#include <cuda_runtime.h>

// MedianFilterLoss, decomposed:
//   loss = sum_i softplus((1-2*t_i)*x_i)                       (base, elementwise)
//        - sum_{runs of ones, len>=3} max-weight subset of w_i = relu(-x_i)
//          with pairwise distance >= 3 (3-state max-plus DP per run)
// 128-thread CTAs, 4096-elem tiles, ~10 CTAs/SM: many small independent
// load/compute phase clocks per SM so DRAM and issue phases of different CTAs
// overlap instead of phase-locking.
// Float staging in smem: element = relu(-x) if t==1, else -1.0 sentinel.
// DP reset = -0.0f; "len>=3" == sign(m0)>=0. Prefix runs: close suppressed.

#define T_LEN 16384
#define TILE  4096
#define NTH   128
#define EPT   32
#define ROWF  36          // floats per thread-row (32 data + 4 pad) = 144B
#define NEGZ  __int_as_float(0x80000000)
#define LN2F  0.6931471805599453f

__device__ float g_partial[4096];
__device__ unsigned int g_done;

__global__ void __launch_bounds__(NTH, 10) mfl_fused(const float* __restrict__ xg,
                                                     const int* __restrict__ tg,
                                                     float* __restrict__ o,
                                                     double inv_n) {
    __shared__ float swf[NTH * ROWF];      // 18432 B
    __shared__ float wsum[NTH / 32];
    __shared__ double sdbl[NTH];
    __shared__ unsigned int s_last;

    const int bid  = blockIdx.x;
    const int row  = bid >> 2;             // 4 tiles per tensor row
    const int qtr  = bid & 3;
    const int base = row * T_LEN + qtr * TILE;
    const int tid  = threadIdx.x;
    const int lane = tid & 31;
    const int wid  = tid >> 5;

    // ---- Phase 1: macro-batched coalesced loads; base loss; float staging ----
    float accR = 0.0f;    // relu terms (+ DP corrections later)
    float accL = 0.0f;    // log2 terms, scaled by ln2 at the end
    const float4* xv = reinterpret_cast<const float4*>(xg + base);
    const int4*   tv = reinterpret_cast<const int4*>(tg + base);
#pragma unroll
    for (int mb = 0; mb < 2; ++mb) {
        float4 vx[4];
        int4   vt[4];
#pragma unroll
        for (int q = 0; q < 4; ++q) {
            int i = (mb * 4 + q) * NTH + tid;
            vx[q] = xv[i];
            vt[q] = tv[i];
        }
#pragma unroll
        for (int q = 0; q < 4; ++q) {
            int i = (mb * 4 + q) * NTH + tid;
            float xs[4] = {vx[q].x, vx[q].y, vx[q].z, vx[q].w};
            int   ts[4] = {vt[q].x, vt[q].y, vt[q].z, vt[q].w};
            float enc[4];
#pragma unroll
            for (int j = 0; j < 4; ++j) {
                float x  = xs[j];
                bool one = (ts[j] != 0);
                float u  = exp2f(fabsf(x) * -1.4426950408889634f);
                accL    += __log2f(1.0f + u);
                float s  = one ? -x : x;
                float w  = fmaxf(s, 0.0f);
                accR    += w;
                enc[j]   = one ? w : -1.0f;
            }
            unsigned r2 = (unsigned)(i >> 3);
            unsigned c2 = (unsigned)(i & 7) * 4u;
            float4 st = {enc[0], enc[1], enc[2], enc[3]};
            *reinterpret_cast<float4*>(&swf[r2 * ROWF + c2]) = st;
        }
    }
    float acc = accR;
    __syncthreads();

    // ---- Phase 2: convergent per-thread DP over 32 contiguous elements ----
    bool suppress;
    if (tid == 0) suppress = qtr ? (tg[base - 1] != 0) : false;
    else          suppress = (swf[(tid - 1) * ROWF + (EPT - 1)] >= 0.0f);

    float m0 = NEGZ, m1 = NEGZ, m2 = NEGZ;
    bool b = false;
    const float* mine = &swf[tid * ROWF];
#pragma unroll
    for (int c = 0; c < EPT / 4; ++c) {               // 8 x LDS.128
        float4 q = *reinterpret_cast<const float4*>(mine + c * 4);
        float fv[4] = {q.x, q.y, q.z, q.w};
#pragma unroll
        for (int e = 0; e < 4; ++e) {
            float f = fv[e];
            b = (f >= 0.0f);
            bool doclose = !b && !suppress && (__float_as_int(m0) >= 0);
            if (doclose) acc -= m2;
            suppress = suppress && b;
            float nm2 = fabsf(fmaxf(m2, m0 + f));
            m0 = b ? m1 : NEGZ;
            m1 = b ? m2 : NEGZ;
            m2 = b ? nm2 : NEGZ;
        }
    }

    // ---- suffix: run open at chunk end -> 8-elem register overlap + rare walk ----
    if (b && !suppress) {
        bool alive = true;
        if (tid < NTH - 1) {
            const float* nb = &swf[(tid + 1) * ROWF];
#pragma unroll
            for (int c = 0; c < 2; ++c) {
                float4 q = *reinterpret_cast<const float4*>(nb + c * 4);
                float fv[4] = {q.x, q.y, q.z, q.w};
#pragma unroll
                for (int e = 0; e < 4; ++e) {
                    float f = fv[e];
                    bool cont = alive && (f >= 0.0f);
                    bool cls  = alive && !cont && (__float_as_int(m0) >= 0);
                    if (cls) acc -= m2;
                    float nm2 = fabsf(fmaxf(m2, m0 + f));
                    m0 = cont ? m1 : m0;
                    m1 = cont ? m2 : m1;
                    m2 = cont ? nm2 : m2;
                    alive = cont;
                }
            }
        }
        if (alive) {                                   // rare: run alive past +8
            int p = (tid + 1) * EPT + ((tid < NTH - 1) ? 8 : 0);
            while (p < TILE) {
                float f = swf[(p >> 5) * ROWF + (p & 31)];
                if (f < 0.0f) break;
                float nm2 = fabsf(fmaxf(m2, m0 + f));
                m0 = m1; m1 = m2; m2 = nm2; ++p;
            }
            if (p == TILE && qtr != 3) {               // spill into rest of row
                int g = base + TILE;
                const int gend = row * T_LEN + T_LEN;
                while (g < gend && tg[g] != 0) {
                    float w = fmaxf(-xg[g], 0.0f);
                    float nm2 = fabsf(fmaxf(m2, m0 + w));
                    m0 = m1; m1 = m2; m2 = nm2; ++g;
                }
            }
            if (__float_as_int(m0) >= 0) acc -= m2;    // close at zero / row end
        }
    }

    acc = fmaf(accL, LN2F, acc);

    // ---- block reduction (4 warps) ----
#pragma unroll
    for (int off = 16; off; off >>= 1)
        acc += __shfl_down_sync(0xFFFFFFFFu, acc, off);
    if (lane == 0) wsum[wid] = acc;
    __syncthreads();
    float blocksum = 0.0f;
    if (wid == 0) {
        float v = (lane < NTH / 32) ? wsum[lane] : 0.0f;
#pragma unroll
        for (int off = 2; off; off >>= 1)
            v += __shfl_down_sync(0xFFFFFFFFu, v, off);
        blocksum = v;
    }

    // ---- last-block-done final reduction (single launch) ----
    if (tid == 0) {
        g_partial[bid] = blocksum;
        __threadfence();
        unsigned old = atomicAdd(&g_done, 1u);
        s_last = (old == gridDim.x - 1) ? 1u : 0u;
    }
    __syncthreads();
    if (s_last) {
        const volatile float* gp = g_partial;
        double sv = 0.0;
        for (int i = tid; i < (int)gridDim.x; i += NTH)
            sv += (double)gp[i];
        sdbl[tid] = sv;
        __syncthreads();
#pragma unroll
        for (int off = NTH / 2; off; off >>= 1) {
            if (tid < off) sdbl[tid] += sdbl[tid + off];
            __syncthreads();
        }
        if (tid == 0) {
            o[0] = (float)(sdbl[0] * inv_n);
            g_done = 0;                                // reset for next graph replay
        }
    }
}

extern "C" void kernel_launch(void* const* d_in, const int* in_sizes, int n_in,
                              void* d_out, int out_size) {
    const float* xg = (const float*)d_in[0];
    const int*   tg = (const int*)d_in[1];
    long long n = (long long)in_sizes[0];      // 1024 * 16384
    int grid = (int)(n / TILE);                // 4096
    mfl_fused<<<grid, NTH>>>(xg, tg, (float*)d_out, 1.0 / (double)n);
}